// round 4
// baseline (speedup 1.0000x reference)
#include <cuda_runtime.h>

// Pure HBM-streaming quadratic form:
//   total = sum over pairs (l1<=l2), weight w in {1,2}:
//           w * sum_s d1[s,:] . O[s,:,:] . d2[s,:],   d = c_in - c_tgt
// Overlap tensors: 356.5 MB read once -> memory-bound (6.36 TB/s measured R3).
// R4: SINGLE fused kernel. Per-block smem staging of the d1/d2 slices
//     (computed on the fly from c_in/c_tgt -> no prep kernel, no g_d),
//     last-block finalize pattern writes out[0] (no zeroing kernel).
//     Schedule kept from R3: 21760 one-unit blocks, 256 thr, IT=4, 8 CTAs/SM.

#define TPB 256
#define IT  4                 // float4 per thread; unit = TPB*IT*4 = 4096 floats
#define NUNITS 21760

__device__ float    g_acc;    // zero-init at load; restored to 0 by last block
__device__ unsigned g_cnt;    // zero-init at load; restored to 0 by last block

struct Ptrs {
    const float4* o[10];      // ovlp blocks, pair order (0,0)(0,1)(0,2)(0,3)(1,1)(1,2)(1,3)(2,2)(2,3)(3,3)
    const float*  cin[4];     // c_in_l0..l3
    const float*  ctg[4];     // c_tgt_l0..l3
};

// One unit (4096 contiguous floats of one ovlp pair). Units never cross an s
// boundary (all D1*D2 are multiples of 4096). Stage d2 row slice + d1 rows
// (weight folded into d1) into smem, then stream.
template <int D1, int D2, int W>
__device__ __forceinline__ float unit_acc(const float4* __restrict__ o,
                                          const float* __restrict__ in1, const float* __restrict__ tg1,
                                          const float* __restrict__ in2, const float* __restrict__ tg2,
                                          int lu, int tid, float* sd1, float4* sd2) {
    constexpr unsigned C4 = D2 / 4;          // float4 columns per row
    const unsigned base4 = (unsigned)lu * (TPB * IT);
    const unsigned s   = base4 / (unsigned)(D1 * C4);     // structure index (const per block)
    const unsigned off = base4 % (unsigned)(D1 * C4);     // within-s float4 offset
    const unsigned r0  = off / C4;                        // first row touched
    const unsigned nr  = (off + TPB * IT - 1) / C4 - r0 + 1;  // rows touched (<=16)

    // stage d2 = in2 - tgt2 for row-slice s (D2 floats, 16B-aligned: D2 % 4 == 0)
    {
        const float4* i2 = (const float4*)(in2 + s * D2);
        const float4* t2 = (const float4*)(tg2 + s * D2);
#pragma unroll
        for (unsigned k = tid; k < C4; k += TPB) {
            float4 a = i2[k], b = t2[k];
            sd2[k] = make_float4(a.x - b.x, a.y - b.y, a.z - b.z, a.w - b.w);
        }
    }
    // stage d1 rows with weight folded
    if ((unsigned)tid < nr) {
        unsigned r = r0 + tid;
        sd1[tid] = (in1[s * D1 + r] - tg1[s * D1 + r]) * (float)W;
    }
    __syncthreads();

    float acc = 0.0f;
#pragma unroll
    for (int it = 0; it < IT; ++it) {
        unsigned loc = off + tid + it * TPB;              // within-s float4 index
        unsigned q  = loc / C4;                           // row (const-div -> mul-shift)
        unsigned c4 = loc - q * C4;
        float4 ov = __ldcs(&o[base4 + tid + it * TPB]);   // streamed, evict-first
        float4 d2 = sd2[c4];                              // conflict-free LDS.128
        float  d1 = sd1[q - r0];                          // LDS broadcast
        acc = fmaf(d1, ov.x * d2.x + ov.y * d2.y + ov.z * d2.z + ov.w * d2.w, acc);
    }
    return acc;
}

// Unit-count prefix sums (unit = 4096 floats):
// (0,0):128 (0,1):512 (0,2):1152 (0,3):2048 (1,1):3200
// (1,2):5120 (1,3):7808 (2,2):11008 (2,3):15488 (3,3):21760
__global__ void __launch_bounds__(TPB, 8) rho_kernel(Ptrs P, float* __restrict__ out) {
    __shared__ float4 sd2[448];       // up to D2=1792 floats
    __shared__ float  sd1[16];
    __shared__ float  ws[TPB / 32];

    const int b = blockIdx.x;
    const int tid = threadIdx.x;
    float acc;
    if      (b <   128) acc = unit_acc< 256,  256, 1>(P.o[0], P.cin[0], P.ctg[0], P.cin[0], P.ctg[0], b,         tid, sd1, sd2);
    else if (b <   512) acc = unit_acc< 256,  768, 2>(P.o[1], P.cin[0], P.ctg[0], P.cin[1], P.ctg[1], b -   128, tid, sd1, sd2);
    else if (b <  1152) acc = unit_acc< 256, 1280, 2>(P.o[2], P.cin[0], P.ctg[0], P.cin[2], P.ctg[2], b -   512, tid, sd1, sd2);
    else if (b <  2048) acc = unit_acc< 256, 1792, 2>(P.o[3], P.cin[0], P.ctg[0], P.cin[3], P.ctg[3], b -  1152, tid, sd1, sd2);
    else if (b <  3200) acc = unit_acc< 768,  768, 1>(P.o[4], P.cin[1], P.ctg[1], P.cin[1], P.ctg[1], b -  2048, tid, sd1, sd2);
    else if (b <  5120) acc = unit_acc< 768, 1280, 2>(P.o[5], P.cin[1], P.ctg[1], P.cin[2], P.ctg[2], b -  3200, tid, sd1, sd2);
    else if (b <  7808) acc = unit_acc< 768, 1792, 2>(P.o[6], P.cin[1], P.ctg[1], P.cin[3], P.ctg[3], b -  5120, tid, sd1, sd2);
    else if (b < 11008) acc = unit_acc<1280, 1280, 1>(P.o[7], P.cin[2], P.ctg[2], P.cin[2], P.ctg[2], b -  7808, tid, sd1, sd2);
    else if (b < 15488) acc = unit_acc<1280, 1792, 2>(P.o[8], P.cin[2], P.ctg[2], P.cin[3], P.ctg[3], b - 11008, tid, sd1, sd2);
    else                acc = unit_acc<1792, 1792, 1>(P.o[9], P.cin[3], P.ctg[3], P.cin[3], P.ctg[3], b - 15488, tid, sd1, sd2);

    // warp reduce
#pragma unroll
    for (int off = 16; off > 0; off >>= 1)
        acc += __shfl_down_sync(0xffffffffu, acc, off);

    if ((tid & 31) == 0) ws[tid >> 5] = acc;
    __syncthreads();
    if (tid == 0) {
        float s = ws[0];
#pragma unroll
        for (int w = 1; w < TPB / 32; ++w) s += ws[w];
        atomicAdd(&g_acc, s);
        __threadfence();
        unsigned old = atomicAdd(&g_cnt, 1u);
        if (old == NUNITS - 1) {
            // all blocks' g_acc adds are visible (release via threadfence + counter)
            float v = atomicExch(&g_acc, 0.0f);   // drain + reset for next replay
            out[0] = v;
            atomicExch(&g_cnt, 0u);               // reset counter for next replay
        }
    }
}

extern "C" void kernel_launch(void* const* d_in, const int* in_sizes, int n_in,
                              void* d_out, int out_size) {
    (void)in_sizes; (void)n_in; (void)out_size;
    Ptrs P;
    // inputs: c_in_l0, c_tgt_l0, c_in_l1, c_tgt_l1, c_in_l2, c_tgt_l2, c_in_l3, c_tgt_l3
    for (int l = 0; l < 4; ++l) {
        P.cin[l] = (const float*)d_in[2 * l];
        P.ctg[l] = (const float*)d_in[2 * l + 1];
    }
    // then the 10 ovlp blocks in pair order
    for (int k = 0; k < 10; ++k) P.o[k] = (const float4*)d_in[8 + k];

    rho_kernel<<<NUNITS, TPB>>>(P, (float*)d_out);
}

// round 5
// speedup vs baseline: 1.0195x; 1.0195x over previous
#include <cuda_runtime.h>

// Pure HBM-streaming quadratic form:
//   total = sum over pairs (l1<=l2), weight w in {1,2}:
//           w * sum_s d1[s,:] . O[s,:,:] . d2[s,:],   d = c_in - c_tgt
// Overlap tensors: 356.5 MB read once -> memory-bound.
// R5: rectangular 16-row x 64-float4-col tiles (same 16KB units / 21760 blocks
//     as R3). Each thread owns ONE d2 column (loaded once, weight folded) and
//     4 rows -> 1 streamed LDG + 1 uniform scalar pair per iter, affine index
//     math, no prep kernel, no smem staging, single fused kernel.

#define TPB 256
#define NUNITS 21760

__device__ float    g_acc;   // zero-init at load; reset by last block each run
__device__ unsigned g_cnt;   // zero-init at load; reset by last block each run

struct Ptrs {
    const float4* o[10];     // ovlp pairs (0,0)(0,1)(0,2)(0,3)(1,1)(1,2)(1,3)(2,2)(2,3)(3,3)
    const float*  cin[4];    // c_in_l0..l3   (flattened [S, D_l])
    const float*  ctg[4];    // c_tgt_l0..l3
};

// One tile: 16 rows x 64 float4 cols of pair (D1, D2=4*C4), weight W.
// lt = local tile index within this pair. tid -> (col, row-quarter).
template <int D1, int C4, int W>
__device__ __forceinline__ float unit_acc(const float4* __restrict__ o,
                                          const float* __restrict__ in1, const float* __restrict__ tg1,
                                          const float4* __restrict__ in2, const float4* __restrict__ tg2,
                                          int lt, int tid) {
    constexpr int TR  = D1 / 16;     // row-tiles per structure
    constexpr int TC  = C4 / 64;     // col-tiles per structure
    constexpr int TPS = TR * TC;     // tiles per structure

    const int s   = lt / TPS;               // compile-time divisor
    const int rem = lt - s * TPS;
    const int tr  = rem / TC;                // compile-time divisor
    const int tc  = rem - tr * TC;

    const int col = tid & 63;
    const int rq  = tid >> 6;                // 0..3
    const int c4  = tc * 64 + col;
    const int r0  = tr * 16 + rq;            // this thread's first row; step 4

    // d2 column (float4), loaded once, weight folded
    const unsigned ci = (unsigned)s * C4 + c4;
    float4 a = in2[ci], b = tg2[ci];
    float4 d2 = make_float4((a.x - b.x) * (float)W, (a.y - b.y) * (float)W,
                            (a.z - b.z) * (float)W, (a.w - b.w) * (float)W);

    const float4* op = o + (unsigned)s * (D1 * C4) + (unsigned)r0 * C4 + c4;
    const float*  i1 = in1 + (unsigned)s * D1 + r0;
    const float*  t1 = tg1 + (unsigned)s * D1 + r0;

    float acc = 0.0f;
#pragma unroll
    for (int it = 0; it < 4; ++it) {
        float4 ov = __ldcs(op + it * 4 * C4);        // streamed, evict-first
        float  d1 = i1[it * 4] - t1[it * 4];         // warp-uniform, L1/L2 hit
        acc = fmaf(d1, ov.x * d2.x + ov.y * d2.y + ov.z * d2.z + ov.w * d2.w, acc);
    }
    return acc;
}

// Tile-count prefix sums (tile = 4096 floats), identical to R3:
// (0,0):128 (0,1):512 (0,2):1152 (0,3):2048 (1,1):3200
// (1,2):5120 (1,3):7808 (2,2):11008 (2,3):15488 (3,3):21760
__global__ void __launch_bounds__(TPB, 8) rho_kernel(Ptrs P, float* __restrict__ out) {
    const int b = blockIdx.x;
    const int tid = threadIdx.x;
    float acc;
    if      (b <   128) acc = unit_acc< 256,  64, 1>(P.o[0], P.cin[0], P.ctg[0], (const float4*)P.cin[0], (const float4*)P.ctg[0], b,         tid);
    else if (b <   512) acc = unit_acc< 256, 192, 2>(P.o[1], P.cin[0], P.ctg[0], (const float4*)P.cin[1], (const float4*)P.ctg[1], b -   128, tid);
    else if (b <  1152) acc = unit_acc< 256, 320, 2>(P.o[2], P.cin[0], P.ctg[0], (const float4*)P.cin[2], (const float4*)P.ctg[2], b -   512, tid);
    else if (b <  2048) acc = unit_acc< 256, 448, 2>(P.o[3], P.cin[0], P.ctg[0], (const float4*)P.cin[3], (const float4*)P.ctg[3], b -  1152, tid);
    else if (b <  3200) acc = unit_acc< 768, 192, 1>(P.o[4], P.cin[1], P.ctg[1], (const float4*)P.cin[1], (const float4*)P.ctg[1], b -  2048, tid);
    else if (b <  5120) acc = unit_acc< 768, 320, 2>(P.o[5], P.cin[1], P.ctg[1], (const float4*)P.cin[2], (const float4*)P.ctg[2], b -  3200, tid);
    else if (b <  7808) acc = unit_acc< 768, 448, 2>(P.o[6], P.cin[1], P.ctg[1], (const float4*)P.cin[3], (const float4*)P.ctg[3], b -  5120, tid);
    else if (b < 11008) acc = unit_acc<1280, 320, 1>(P.o[7], P.cin[2], P.ctg[2], (const float4*)P.cin[2], (const float4*)P.ctg[2], b -  7808, tid);
    else if (b < 15488) acc = unit_acc<1280, 448, 2>(P.o[8], P.cin[2], P.ctg[2], (const float4*)P.cin[3], (const float4*)P.ctg[3], b - 11008, tid);
    else                acc = unit_acc<1792, 448, 1>(P.o[9], P.cin[3], P.ctg[3], (const float4*)P.cin[3], (const float4*)P.ctg[3], b - 15488, tid);

    // warp reduce
#pragma unroll
    for (int off = 16; off > 0; off >>= 1)
        acc += __shfl_down_sync(0xffffffffu, acc, off);

    __shared__ float ws[TPB / 32];
    if ((tid & 31) == 0) ws[tid >> 5] = acc;
    __syncthreads();
    if (tid == 0) {
        float s = ws[0];
#pragma unroll
        for (int w = 1; w < TPB / 32; ++w) s += ws[w];
        atomicAdd(&g_acc, s);
        __threadfence();
        unsigned old = atomicAdd(&g_cnt, 1u);
        if (old == NUNITS - 1) {
            float v = atomicExch(&g_acc, 0.0f);   // drain + reset for next replay
            out[0] = v;
            atomicExch(&g_cnt, 0u);               // reset counter for next replay
        }
    }
}

extern "C" void kernel_launch(void* const* d_in, const int* in_sizes, int n_in,
                              void* d_out, int out_size) {
    (void)in_sizes; (void)n_in; (void)out_size;
    Ptrs P;
    // inputs: c_in_l0, c_tgt_l0, ..., c_in_l3, c_tgt_l3, then 10 ovlp blocks
    for (int l = 0; l < 4; ++l) {
        P.cin[l] = (const float*)d_in[2 * l];
        P.ctg[l] = (const float*)d_in[2 * l + 1];
    }
    for (int k = 0; k < 10; ++k) P.o[k] = (const float4*)d_in[8 + k];

    rho_kernel<<<NUNITS, TPB>>>(P, (float*)d_out);
}

// round 6
// speedup vs baseline: 1.0296x; 1.0099x over previous
#include <cuda_runtime.h>

// Pure HBM-streaming quadratic form:
//   total = sum over pairs (l1<=l2), weight w in {1,2}:
//           w * sum_s d1[s,:] . O[s,:,:] . d2[s,:],   d = c_in - c_tgt
// Overlap tensors: 356.5 MB read once -> memory-bound.
// R5: rectangular 16-row x 64-float4-col tiles (same 16KB units / 21760 blocks
//     as R3). Each thread owns ONE d2 column (loaded once, weight folded) and
//     4 rows -> 1 streamed LDG + 1 uniform scalar pair per iter, affine index
//     math, no prep kernel, no smem staging, single fused kernel.

#define TPB 256
#define NUNITS 21760

__device__ float    g_acc;   // zero-init at load; reset by last block each run
__device__ unsigned g_cnt;   // zero-init at load; reset by last block each run

struct Ptrs {
    const float4* o[10];     // ovlp pairs (0,0)(0,1)(0,2)(0,3)(1,1)(1,2)(1,3)(2,2)(2,3)(3,3)
    const float*  cin[4];    // c_in_l0..l3   (flattened [S, D_l])
    const float*  ctg[4];    // c_tgt_l0..l3
};

// One tile: 16 rows x 64 float4 cols of pair (D1, D2=4*C4), weight W.
// lt = local tile index within this pair. tid -> (col, row-quarter).
template <int D1, int C4, int W>
__device__ __forceinline__ float unit_acc(const float4* __restrict__ o,
                                          const float* __restrict__ in1, const float* __restrict__ tg1,
                                          const float4* __restrict__ in2, const float4* __restrict__ tg2,
                                          int lt, int tid) {
    constexpr int TR  = D1 / 16;     // row-tiles per structure
    constexpr int TC  = C4 / 64;     // col-tiles per structure
    constexpr int TPS = TR * TC;     // tiles per structure

    const int s   = lt / TPS;               // compile-time divisor
    const int rem = lt - s * TPS;
    const int tr  = rem / TC;                // compile-time divisor
    const int tc  = rem - tr * TC;

    const int col = tid & 63;
    const int rq  = tid >> 6;                // 0..3
    const int c4  = tc * 64 + col;
    const int r0  = tr * 16 + rq;            // this thread's first row; step 4

    // d2 column (float4), loaded once, weight folded
    const unsigned ci = (unsigned)s * C4 + c4;
    float4 a = in2[ci], b = tg2[ci];
    float4 d2 = make_float4((a.x - b.x) * (float)W, (a.y - b.y) * (float)W,
                            (a.z - b.z) * (float)W, (a.w - b.w) * (float)W);

    const float4* op = o + (unsigned)s * (D1 * C4) + (unsigned)r0 * C4 + c4;
    const float*  i1 = in1 + (unsigned)s * D1 + r0;
    const float*  t1 = tg1 + (unsigned)s * D1 + r0;

    float acc = 0.0f;
#pragma unroll
    for (int it = 0; it < 4; ++it) {
        float4 ov = __ldcs(op + it * 4 * C4);        // streamed, evict-first
        float  d1 = i1[it * 4] - t1[it * 4];         // warp-uniform, L1/L2 hit
        acc = fmaf(d1, ov.x * d2.x + ov.y * d2.y + ov.z * d2.z + ov.w * d2.w, acc);
    }
    return acc;
}

// Tile-count prefix sums (tile = 4096 floats), identical to R3:
// (0,0):128 (0,1):512 (0,2):1152 (0,3):2048 (1,1):3200
// (1,2):5120 (1,3):7808 (2,2):11008 (2,3):15488 (3,3):21760
__global__ void __launch_bounds__(TPB, 8) rho_kernel(Ptrs P, float* __restrict__ out) {
    const int b = blockIdx.x;
    const int tid = threadIdx.x;
    float acc;
    if      (b <   128) acc = unit_acc< 256,  64, 1>(P.o[0], P.cin[0], P.ctg[0], (const float4*)P.cin[0], (const float4*)P.ctg[0], b,         tid);
    else if (b <   512) acc = unit_acc< 256, 192, 2>(P.o[1], P.cin[0], P.ctg[0], (const float4*)P.cin[1], (const float4*)P.ctg[1], b -   128, tid);
    else if (b <  1152) acc = unit_acc< 256, 320, 2>(P.o[2], P.cin[0], P.ctg[0], (const float4*)P.cin[2], (const float4*)P.ctg[2], b -   512, tid);
    else if (b <  2048) acc = unit_acc< 256, 448, 2>(P.o[3], P.cin[0], P.ctg[0], (const float4*)P.cin[3], (const float4*)P.ctg[3], b -  1152, tid);
    else if (b <  3200) acc = unit_acc< 768, 192, 1>(P.o[4], P.cin[1], P.ctg[1], (const float4*)P.cin[1], (const float4*)P.ctg[1], b -  2048, tid);
    else if (b <  5120) acc = unit_acc< 768, 320, 2>(P.o[5], P.cin[1], P.ctg[1], (const float4*)P.cin[2], (const float4*)P.ctg[2], b -  3200, tid);
    else if (b <  7808) acc = unit_acc< 768, 448, 2>(P.o[6], P.cin[1], P.ctg[1], (const float4*)P.cin[3], (const float4*)P.ctg[3], b -  5120, tid);
    else if (b < 11008) acc = unit_acc<1280, 320, 1>(P.o[7], P.cin[2], P.ctg[2], (const float4*)P.cin[2], (const float4*)P.ctg[2], b -  7808, tid);
    else if (b < 15488) acc = unit_acc<1280, 448, 2>(P.o[8], P.cin[2], P.ctg[2], (const float4*)P.cin[3], (const float4*)P.ctg[3], b - 11008, tid);
    else                acc = unit_acc<1792, 448, 1>(P.o[9], P.cin[3], P.ctg[3], (const float4*)P.cin[3], (const float4*)P.ctg[3], b - 15488, tid);

    // warp reduce
#pragma unroll
    for (int off = 16; off > 0; off >>= 1)
        acc += __shfl_down_sync(0xffffffffu, acc, off);

    __shared__ float ws[TPB / 32];
    if ((tid & 31) == 0) ws[tid >> 5] = acc;
    __syncthreads();
    if (tid == 0) {
        float s = ws[0];
#pragma unroll
        for (int w = 1; w < TPB / 32; ++w) s += ws[w];
        atomicAdd(&g_acc, s);
        __threadfence();
        unsigned old = atomicAdd(&g_cnt, 1u);
        if (old == NUNITS - 1) {
            float v = atomicExch(&g_acc, 0.0f);   // drain + reset for next replay
            out[0] = v;
            atomicExch(&g_cnt, 0u);               // reset counter for next replay
        }
    }
}

extern "C" void kernel_launch(void* const* d_in, const int* in_sizes, int n_in,
                              void* d_out, int out_size) {
    (void)in_sizes; (void)n_in; (void)out_size;
    Ptrs P;
    // inputs: c_in_l0, c_tgt_l0, ..., c_in_l3, c_tgt_l3, then 10 ovlp blocks
    for (int l = 0; l < 4; ++l) {
        P.cin[l] = (const float*)d_in[2 * l];
        P.ctg[l] = (const float*)d_in[2 * l + 1];
    }
    for (int k = 0; k < 10; ++k) P.o[k] = (const float4*)d_in[8 + k];

    rho_kernel<<<NUNITS, TPB>>>(P, (float*)d_out);
}